// round 16
// baseline (speedup 1.0000x reference)
#include <cuda_runtime.h>
#include <math.h>

#define DIMC   1024
#define NHEADS 16
#define HDIM   64
#define BATCH  4
#define NQ     4096
#define NCTX   256

// Scratch (no allocations allowed) ------------------------------------------
__device__ float g_q [BATCH * NQ   * DIMC];   // 64 MB (normed+roped, tf32)
__device__ float g_k [BATCH * NCTX * DIMC];   //  4 MB (normed, tf32)
__device__ float g_v [BATCH * NCTX * DIMC];   //  4 MB (tf32)
__device__ float g_ao[BATCH * NQ   * DIMC];   // 64 MB
__device__ float g_xr[BATCH * NQ   * DIMC];   // 64 MB  x pre-rounded tf32
__device__ float g_cr[BATCH * NCTX * DIMC];   //  4 MB  c pre-rounded
__device__ float g_wt[4][DIMC * DIMC];        // 16 MB  W^T, tf32-rounded

__device__ __forceinline__ float tf32f(float f) {
    unsigned r;
    asm("cvt.rna.tf32.f32 %0, %1;" : "=r"(r) : "f"(f));
    return __uint_as_float(r);
}

#define MMA_TF32(C, a0, a1, a2, a3, b0, b1)                                   \
    asm volatile(                                                             \
        "mma.sync.aligned.m16n8k8.row.col.f32.tf32.tf32.f32 "                 \
        "{%0,%1,%2,%3}, {%4,%5,%6,%7}, {%8,%9}, {%0,%1,%2,%3};"               \
        : "+f"((C)[0]), "+f"((C)[1]), "+f"((C)[2]), "+f"((C)[3])              \
        : "r"(a0), "r"(a1), "r"(a2), "r"(a3), "r"(b0), "r"(b1))

#define LDSM4(r0, r1, r2, r3, saddr)                                          \
    asm volatile("ldmatrix.sync.aligned.m8n8.x4.shared.b16 {%0,%1,%2,%3}, [%4];" \
        : "=r"(r0), "=r"(r1), "=r"(r2), "=r"(r3) : "r"(saddr))

#define CPA16(saddr, gptr) \
    asm volatile("cp.async.cg.shared.global [%0], [%1], 16;" :: "r"(saddr), "l"(gptr))

// ===========================================================================
// Prep kernels
// ===========================================================================
__global__ __launch_bounds__(256) void round_tf32(
    const float* __restrict__ s, float* __restrict__ d, int n4)
{
    int i = blockIdx.x * blockDim.x + threadIdx.x;
    if (i < n4) {
        float4 v = ((const float4*)s)[i];
        v.x = tf32f(v.x); v.y = tf32f(v.y);
        v.z = tf32f(v.z); v.w = tf32f(v.w);
        ((float4*)d)[i] = v;
    }
}

__global__ __launch_bounds__(256) void trans_round_w(
    const float* __restrict__ s0, const float* __restrict__ s1,
    const float* __restrict__ s2, const float* __restrict__ s3,
    float* __restrict__ d)
{
    const float* s = (blockIdx.z == 0) ? s0 : (blockIdx.z == 1) ? s1
                   : (blockIdx.z == 2) ? s2 : s3;
    float* dd = d + (long)blockIdx.z * (DIMC * DIMC);
    __shared__ float t[32][33];
    int tx = threadIdx.x & 31, ty = threadIdx.x >> 5;
    int bx = blockIdx.x * 32, by = blockIdx.y * 32;
#pragma unroll
    for (int i = 0; i < 32; i += 8)
        t[ty + i][tx] = tf32f(s[(long)(by + ty + i) * DIMC + bx + tx]);
    __syncthreads();
#pragma unroll
    for (int i = 0; i < 32; i += 8)
        dd[(long)(bx + ty + i) * DIMC + by + tx] = t[tx][ty + i];
}

// ===========================================================================
// tf32 GEMM, B pre-transposed (k-major). 128x128x32 tile, 256 thr, ldmatrix.
// R14 pipelining (issue-then-wait_group 1). Templated epilogue:
//   MODE 0: (+bias) (+tf32 round if ROUNDC)
//   MODE 1: per-head RMSNorm * nw, tf32 round      (K path)
//   MODE 2: per-head RMSNorm * nw + RoPE, tf32 round (Q path)
// ===========================================================================
#define AST 36
#define STAGE_F (2 * 128 * AST)
#define STAGE_B (STAGE_F * 4)
#define GEMM_SMEM (2 * STAGE_B)          // 73728 B (also covers epilogue bufs)

template<int MODE, int ROUNDC>
__global__ __launch_bounds__(256) void gemm_t(
    const float* __restrict__ A, const float* __restrict__ Bt,
    const float* __restrict__ bias, const float* __restrict__ nw,
    const float* __restrict__ rcos, const float* __restrict__ rsin,
    float* __restrict__ C, int M, int N, int K)
{
    extern __shared__ float sh[];

    const int t    = threadIdx.x;
    const int lane = t & 31;
    const int w    = t >> 5;
    const int wm   = (w & 1) * 64;
    const int wn   = (w >> 1) * 32;
    const int m0   = blockIdx.y * 128;
    const int n0   = blockIdx.x * 128;

    const unsigned shu = (unsigned)__cvta_generic_to_shared(sh);

    float acc[4][4][4];
#pragma unroll
    for (int mt = 0; mt < 4; mt++)
#pragma unroll
        for (int nt = 0; nt < 4; nt++)
#pragma unroll
            for (int i = 0; i < 4; i++) acc[mt][nt][i] = 0.f;

#define ISSUE(s, k0)                                                          \
    {                                                                         \
        unsigned abase = shu + (s) * STAGE_B;                                 \
        unsigned bbase = abase + 128 * AST * 4;                               \
        _Pragma("unroll")                                                     \
        for (int j = 0; j < 4; j++) {                                         \
            int idx = t + j * 256;                                            \
            int r = idx >> 3, c4 = (idx & 7) << 2;                            \
            CPA16(abase + (unsigned)(r * AST + c4) * 4,                       \
                  A + (long)(m0 + r) * K + (k0) + c4);                        \
            CPA16(bbase + (unsigned)(r * AST + c4) * 4,                       \
                  Bt + (long)(n0 + r) * K + (k0) + c4);                       \
        }                                                                     \
        asm volatile("cp.async.commit_group;");                               \
    }

    const int aSel = ((lane >> 3) & 1) * 8 + (lane & 7);
    const int cSel = (lane >> 4) * 4;
    const int bRowSel = (lane >> 4) * 8 + (lane & 7);
    const int bColSel = ((lane >> 3) & 1) * 4;

    const int niter = K >> 5;
    ISSUE(0, 0);

    for (int it = 0; it < niter; it++) {
        if (it + 1 < niter) {
            ISSUE((it + 1) & 1, (it + 1) << 5);
            asm volatile("cp.async.wait_group 1;");
        } else {
            asm volatile("cp.async.wait_group 0;");
        }
        __syncthreads();

        unsigned as_u = shu + (it & 1) * STAGE_B;
        unsigned bs_u = as_u + 128 * AST * 4;

#pragma unroll
        for (int kk = 0; kk < 32; kk += 8) {
            unsigned af[4][4], bf[4][2];
#pragma unroll
            for (int mt = 0; mt < 4; mt++) {
                unsigned ad = as_u +
                    (unsigned)((wm + mt * 16 + aSel) * AST + kk + cSel) * 4;
                LDSM4(af[mt][0], af[mt][1], af[mt][2], af[mt][3], ad);
            }
#pragma unroll
            for (int p = 0; p < 2; p++) {
                unsigned bd = bs_u +
                    (unsigned)((wn + p * 16 + bRowSel) * AST + kk + bColSel) * 4;
                LDSM4(bf[2 * p][0], bf[2 * p][1], bf[2 * p + 1][0],
                      bf[2 * p + 1][1], bd);
            }
#pragma unroll
            for (int mt = 0; mt < 4; mt++)
#pragma unroll
                for (int nt = 0; nt < 4; nt++)
                    MMA_TF32(acc[mt][nt], af[mt][0], af[mt][1], af[mt][2],
                             af[mt][3], bf[nt][0], bf[nt][1]);
        }
        __syncthreads();
    }

    const int qrow = lane >> 2;

    if (MODE == 0) {
#pragma unroll
        for (int nt = 0; nt < 4; nt++) {
            int col = n0 + wn + nt * 8 + 2 * (lane & 3);
            float bb0 = bias ? bias[col]     : 0.f;
            float bb1 = bias ? bias[col + 1] : 0.f;
#pragma unroll
            for (int mt = 0; mt < 4; mt++) {
                int row = m0 + wm + mt * 16 + qrow;
                float2 r0, r1;
                r0.x = acc[mt][nt][0] + bb0; r0.y = acc[mt][nt][1] + bb1;
                r1.x = acc[mt][nt][2] + bb0; r1.y = acc[mt][nt][3] + bb1;
                if (ROUNDC) {
                    r0.x = tf32f(r0.x); r0.y = tf32f(r0.y);
                    r1.x = tf32f(r1.x); r1.y = tf32f(r1.y);
                }
                *(float2*)&C[(long)row * N + col]       = r0;
                *(float2*)&C[(long)(row + 8) * N + col] = r1;
            }
        }
    } else {
        // ---- fused RMSNorm (+RoPE) epilogue ------------------------------
        float* ssb = sh;                 // [2][128] partial sums
        float* vt  = sh + 512;           // [128][132] (MODE 2 only)
        const int ny = w >> 1;

        float ssA[4], ssB[4];
#pragma unroll
        for (int mt = 0; mt < 4; mt++) {
            float a = 0.f, b2 = 0.f;
#pragma unroll
            for (int nt = 0; nt < 4; nt++) {
                a  += acc[mt][nt][0] * acc[mt][nt][0]
                    + acc[mt][nt][1] * acc[mt][nt][1];
                b2 += acc[mt][nt][2] * acc[mt][nt][2]
                    + acc[mt][nt][3] * acc[mt][nt][3];
            }
            a  += __shfl_xor_sync(0xffffffffu, a, 1);
            a  += __shfl_xor_sync(0xffffffffu, a, 2);
            b2 += __shfl_xor_sync(0xffffffffu, b2, 1);
            b2 += __shfl_xor_sync(0xffffffffu, b2, 2);
            ssA[mt] = a; ssB[mt] = b2;
        }
        if ((lane & 3) == 0) {
#pragma unroll
            for (int mt = 0; mt < 4; mt++) {
                int rl = wm + 16 * mt + qrow;
                ssb[ny * 128 + rl]     = ssA[mt];
                ssb[ny * 128 + rl + 8] = ssB[mt];
            }
        }
        __syncthreads();

#pragma unroll
        for (int mt = 0; mt < 4; mt++) {
            int rl = wm + 16 * mt + qrow;
            float invA = rsqrtf((ssA[mt] + ssb[(ny ^ 1) * 128 + rl])
                                * (1.f / 64.f) + 1e-6f);
            float invB = rsqrtf((ssB[mt] + ssb[(ny ^ 1) * 128 + rl + 8])
                                * (1.f / 64.f) + 1e-6f);
#pragma unroll
            for (int nt = 0; nt < 4; nt++) {
                int cl = wn + nt * 8 + 2 * (lane & 3);
                float w0 = nw[cl & 63], w1 = nw[(cl + 1) & 63];
                acc[mt][nt][0] *= invA * w0;
                acc[mt][nt][1] *= invA * w1;
                acc[mt][nt][2] *= invB * w0;
                acc[mt][nt][3] *= invB * w1;
            }
        }

        if (MODE == 1) {
#pragma unroll
            for (int mt = 0; mt < 4; mt++) {
                int row = m0 + wm + 16 * mt + qrow;
#pragma unroll
                for (int nt = 0; nt < 4; nt++) {
                    int col = n0 + wn + nt * 8 + 2 * (lane & 3);
                    *(float2*)&C[(long)row * N + col] =
                        make_float2(tf32f(acc[mt][nt][0]), tf32f(acc[mt][nt][1]));
                    *(float2*)&C[(long)(row + 8) * N + col] =
                        make_float2(tf32f(acc[mt][nt][2]), tf32f(acc[mt][nt][3]));
                }
            }
        } else {
            // Q path: RoPE via smem tile exchange (d <-> d^32)
#pragma unroll
            for (int mt = 0; mt < 4; mt++) {
                int rl = wm + 16 * mt + qrow;
#pragma unroll
                for (int nt = 0; nt < 4; nt++) {
                    int cl = wn + nt * 8 + 2 * (lane & 3);
                    *(float2*)&vt[rl * 132 + cl] =
                        make_float2(acc[mt][nt][0], acc[mt][nt][1]);
                    *(float2*)&vt[(rl + 8) * 132 + cl] =
                        make_float2(acc[mt][nt][2], acc[mt][nt][3]);
                }
            }
            __syncthreads();
#pragma unroll
            for (int mt = 0; mt < 4; mt++) {
                int rl = wm + 16 * mt + qrow;
                int nA = (m0 + rl)     & (NQ - 1);
                int nB = (m0 + rl + 8) & (NQ - 1);
#pragma unroll
                for (int nt = 0; nt < 4; nt++) {
                    int cl = wn + nt * 8 + 2 * (lane & 3);
                    int d  = cl & 63;
                    float2 cA = *(const float2*)&rcos[nA * 64 + d];
                    float2 sA = *(const float2*)&rsin[nA * 64 + d];
                    float2 cB = *(const float2*)&rcos[nB * 64 + d];
                    float2 sB = *(const float2*)&rsin[nB * 64 + d];
                    float p0A = vt[rl * 132 + (cl ^ 32)];
                    float p1A = vt[rl * 132 + ((cl + 1) ^ 32)];
                    float p0B = vt[(rl + 8) * 132 + (cl ^ 32)];
                    float p1B = vt[(rl + 8) * 132 + ((cl + 1) ^ 32)];
                    float sgn = (cl & 32) ? 1.f : -1.f;
                    float o0A = acc[mt][nt][0] * cA.x + sgn * p0A * sA.x;
                    float o1A = acc[mt][nt][1] * cA.y + sgn * p1A * sA.y;
                    float o0B = acc[mt][nt][2] * cB.x + sgn * p0B * sB.x;
                    float o1B = acc[mt][nt][3] * cB.y + sgn * p1B * sB.y;
                    int row = m0 + rl, col = n0 + cl;
                    *(float2*)&C[(long)row * N + col] =
                        make_float2(tf32f(o0A), tf32f(o1A));
                    *(float2*)&C[(long)(row + 8) * N + col] =
                        make_float2(tf32f(o0B), tf32f(o1B));
                }
            }
        }
    }
}

// ===========================================================================
// Register-resident tensor-core attention.
// CTA = 128 q-rows x 1 head x 1 batch; warp w owns 16 q-rows x 256 ctx.
// QK^T -> regs; quad-shuffle softmax; PV via per-warp smem P (aliases Qs/Ks)
// + ldmatrix, V b-frags ALSO via ldmatrix from transposed Vt[d][j].
// ===========================================================================
#define ATQ 0
#define ATK (128 * 68)                   // 8704
#define ATV (ATK + 256 * 68)             // 26112
#define VTS 260
#define ATT_FLOATS (ATV + 64 * VTS)      // 42752 floats = 171008 B
#define PSTR 132
#define PBUF_W (16 * PSTR)               // P buffers alias Qs+Ks (dead)

__global__ __launch_bounds__(256) void attn_mma(
    const float* __restrict__ q, const float* __restrict__ k,
    const float* __restrict__ v, float* __restrict__ ao)
{
    extern __shared__ float sm[];
    float* Qs = sm + ATQ;
    float* Ks = sm + ATK;
    float* Vt = sm + ATV;
    const unsigned shu  = (unsigned)__cvta_generic_to_shared(sm);
    const unsigned qs_u = shu;
    const unsigned ks_u = shu + ATK * 4;
    const unsigned vt_u = shu + ATV * 4;

    const int t  = threadIdx.x;
    const int nt = blockIdx.x, h = blockIdx.y, b = blockIdx.z;
    const int qrow0  = b * NQ + nt * 128;
    const int kvrow0 = b * NCTX;
    const int cbase  = h * HDIM;

    for (int i4 = t; i4 < 128 * 16; i4 += 256) {
        int i = i4 >> 4, d4 = (i4 & 15) << 2;
        *(float4*)&Qs[i * 68 + d4] =
            *(const float4*)&q[(long)(qrow0 + i) * DIMC + cbase + d4];
    }
    for (int i4 = t; i4 < 256 * 16; i4 += 256) {
        int j = i4 >> 4, d4 = (i4 & 15) << 2;
        *(float4*)&Ks[j * 68 + d4] =
            *(const float4*)&k[(long)(kvrow0 + j) * DIMC + cbase + d4];
    }
    // V transposed: Vt[d][j] (coalesced gmem read; 4-way-conflict smem write,
    // one-time cost; enables ldmatrix b-frags in PV)
    for (int idx = t; idx < 256 * 64; idx += 256) {
        int j = idx >> 6, d = idx & 63;
        Vt[d * VTS + j] = v[(long)(kvrow0 + j) * DIMC + cbase + d];
    }
    __syncthreads();

    const int lane = t & 31;
    const int w    = t >> 5;
    const int qr   = w * 16;

    const int aSel = ((lane >> 3) & 1) * 8 + (lane & 7);
    const int cSel = (lane >> 4) * 4;
    const int bRowSel = (lane >> 4) * 8 + (lane & 7);
    const int bColSel = ((lane >> 3) & 1) * 4;

    // ---- S = Q K^T (16 x 256 per warp, in registers) ---------------------
    float acc[32][4];
#pragma unroll
    for (int n = 0; n < 32; n++)
#pragma unroll
        for (int i = 0; i < 4; i++) acc[n][i] = 0.f;

#pragma unroll
    for (int ks = 0; ks < 8; ks++) {
        int d0 = ks * 8;
        unsigned a0, a1, a2, a3;
        LDSM4(a0, a1, a2, a3,
              qs_u + (unsigned)((qr + aSel) * 68 + d0 + cSel) * 4);
#pragma unroll
        for (int p = 0; p < 16; p++) {
            unsigned b0, b1, b2, b3;
            LDSM4(b0, b1, b2, b3,
                  ks_u + (unsigned)((p * 16 + bRowSel) * 68 + d0 + bColSel) * 4);
            MMA_TF32(acc[2 * p],     a0, a1, a2, a3, b0, b1);
            MMA_TF32(acc[2 * p + 1], a0, a1, a2, a3, b2, b3);
        }
    }
    __syncthreads();   // Qs/Ks reads done (P buffers alias them)

    // ---- softmax (rows on lane-quads) ------------------------------------
    const float scale = 0.125f;
    float mxA = -1e30f, mxB = -1e30f;
#pragma unroll
    for (int n = 0; n < 32; n++) {
        mxA = fmaxf(mxA, fmaxf(acc[n][0], acc[n][1]));
        mxB = fmaxf(mxB, fmaxf(acc[n][2], acc[n][3]));
    }
    mxA = fmaxf(mxA, __shfl_xor_sync(0xffffffffu, mxA, 1));
    mxA = fmaxf(mxA, __shfl_xor_sync(0xffffffffu, mxA, 2));
    mxB = fmaxf(mxB, __shfl_xor_sync(0xffffffffu, mxB, 1));
    mxB = fmaxf(mxB, __shfl_xor_sync(0xffffffffu, mxB, 2));
    mxA *= scale; mxB *= scale;

    float sA = 0.f, sB = 0.f;
#pragma unroll
    for (int n = 0; n < 32; n++) {
        acc[n][0] = __expf(acc[n][0] * scale - mxA); sA += acc[n][0];
        acc[n][1] = __expf(acc[n][1] * scale - mxA); sA += acc[n][1];
        acc[n][2] = __expf(acc[n][2] * scale - mxB); sB += acc[n][2];
        acc[n][3] = __expf(acc[n][3] * scale - mxB); sB += acc[n][3];
    }
    sA += __shfl_xor_sync(0xffffffffu, sA, 1);
    sA += __shfl_xor_sync(0xffffffffu, sA, 2);
    sB += __shfl_xor_sync(0xffffffffu, sB, 1);
    sB += __shfl_xor_sync(0xffffffffu, sB, 2);
    float invA = 1.f / sA, invB = 1.f / sB;
#pragma unroll
    for (int n = 0; n < 32; n++) {
        acc[n][0] = tf32f(acc[n][0] * invA);
        acc[n][1] = tf32f(acc[n][1] * invA);
        acc[n][2] = tf32f(acc[n][2] * invB);
        acc[n][3] = tf32f(acc[n][3] * invB);
    }

    // ---- O = P V: P staged per-warp + ldmatrix; V frags via ldmatrix -----
    float* Pb = sm + w * PBUF_W;
    const unsigned pb_u = shu + (unsigned)(w * PBUF_W) * 4;

    float oacc[8][4];
#pragma unroll
    for (int dt = 0; dt < 8; dt++)
#pragma unroll
        for (int i = 0; i < 4; i++) oacc[dt][i] = 0.f;

#pragma unroll
    for (int hf = 0; hf < 2; hf++) {
#pragma unroll
        for (int nl = 0; nl < 16; nl++) {
            int n = 16 * hf + nl;
            int base = (lane >> 2) * PSTR + nl * 8 + 2 * (lane & 3);
            *(float2*)&Pb[base]            = make_float2(acc[n][0], acc[n][1]);
            *(float2*)&Pb[base + 8 * PSTR] = make_float2(acc[n][2], acc[n][3]);
        }
        __syncwarp();
#pragma unroll
        for (int ksl = 0; ksl < 16; ksl++) {
            unsigned a0, a1, a2, a3;
            LDSM4(a0, a1, a2, a3,
                  pb_u + (unsigned)(aSel * PSTR + ksl * 8 + cSel) * 4);
            int j0 = 128 * hf + ksl * 8;
#pragma unroll
            for (int p = 0; p < 4; p++) {   // covers d-tiles 2p, 2p+1
                unsigned b0, b1, b2, b3;
                LDSM4(b0, b1, b2, b3,
                      vt_u + (unsigned)((p * 16 + bRowSel) * VTS + j0 + bColSel) * 4);
                MMA_TF32(oacc[2 * p],     a0, a1, a2, a3, b0, b1);
                MMA_TF32(oacc[2 * p + 1], a0, a1, a2, a3, b2, b3);
            }
        }
        __syncwarp();   // P reads done before next half overwrites
    }

    // store O (tf32-rounded; feeds O-proj GEMM)
#pragma unroll
    for (int dt = 0; dt < 8; dt++) {
        long row = qrow0 + qr + (lane >> 2);
        int  col = cbase + dt * 8 + 2 * (lane & 3);
        float2 r0, r1;
        r0.x = tf32f(oacc[dt][0]); r0.y = tf32f(oacc[dt][1]);
        r1.x = tf32f(oacc[dt][2]); r1.y = tf32f(oacc[dt][3]);
        *(float2*)&ao[row * DIMC + col]       = r0;
        *(float2*)&ao[(row + 8) * DIMC + col] = r1;
    }
}

// ---------------------------------------------------------------------------
extern "C" void kernel_launch(void* const* d_in, const int* in_sizes, int n_in,
                              void* d_out, int out_size)
{
    const float* x  = (const float*)d_in[0];
    const float* c  = (const float*)d_in[1];
    const float* rc = (const float*)d_in[2];
    const float* rs = (const float*)d_in[3];
    const float* Wq = (const float*)d_in[4];
    const float* Wk = (const float*)d_in[5];
    const float* Wv = (const float*)d_in[6];
    const float* Wo = (const float*)d_in[7];
    const float* bo = (const float*)d_in[8];
    const float* qw = (const float*)d_in[9];
    const float* kw = (const float*)d_in[10];
    float* out = (float*)d_out;

    float *q, *k, *v, *ao, *xr, *cr, *wt;
    cudaGetSymbolAddress((void**)&q,  g_q);
    cudaGetSymbolAddress((void**)&k,  g_k);
    cudaGetSymbolAddress((void**)&v,  g_v);
    cudaGetSymbolAddress((void**)&ao, g_ao);
    cudaGetSymbolAddress((void**)&xr, g_xr);
    cudaGetSymbolAddress((void**)&cr, g_cr);
    cudaGetSymbolAddress((void**)&wt, g_wt);

    cudaFuncSetAttribute(gemm_t<0, 0>, cudaFuncAttributeMaxDynamicSharedMemorySize, GEMM_SMEM);
    cudaFuncSetAttribute(gemm_t<0, 1>, cudaFuncAttributeMaxDynamicSharedMemorySize, GEMM_SMEM);
    cudaFuncSetAttribute(gemm_t<1, 1>, cudaFuncAttributeMaxDynamicSharedMemorySize, GEMM_SMEM);
    cudaFuncSetAttribute(gemm_t<2, 1>, cudaFuncAttributeMaxDynamicSharedMemorySize, GEMM_SMEM);
    cudaFuncSetAttribute(attn_mma, cudaFuncAttributeMaxDynamicSharedMemorySize,
                         ATT_FLOATS * (int)sizeof(float));

    // ---- prep: round activations, transpose+round weights ----------------
    {
        int n4x = BATCH * NQ * DIMC / 4;
        round_tf32<<<n4x / 256, 256>>>(x, xr, n4x);
        int n4c = BATCH * NCTX * DIMC / 4;
        round_tf32<<<n4c / 256, 256>>>(c, cr, n4c);
        trans_round_w<<<dim3(32, 32, 4), 256>>>(Wq, Wk, Wv, Wo, wt);
    }
    const float* wqt = wt;
    const float* wkt = wt + (long)1 * DIMC * DIMC;
    const float* wvt = wt + (long)2 * DIMC * DIMC;
    const float* wot = wt + (long)3 * DIMC * DIMC;

    // ---- Q projection + fused RMSNorm + RoPE -----------------------------
    gemm_t<2, 1><<<dim3(8, 128), 256, GEMM_SMEM>>>(
        xr, wqt, nullptr, qw, rc, rs, q, BATCH * NQ, DIMC, DIMC);

    // ---- K (fused RMSNorm) and V (plain, tf32-rounded) -------------------
    gemm_t<1, 1><<<dim3(8, 8), 256, GEMM_SMEM>>>(
        cr, wkt, nullptr, kw, nullptr, nullptr, k, BATCH * NCTX, DIMC, DIMC);
    gemm_t<0, 1><<<dim3(8, 8), 256, GEMM_SMEM>>>(
        cr, wvt, nullptr, nullptr, nullptr, nullptr, v, BATCH * NCTX, DIMC, DIMC);

    // ---- attention --------------------------------------------------------
    attn_mma<<<dim3(NQ / 128, NHEADS, BATCH), 256,
               ATT_FLOATS * (int)sizeof(float)>>>(q, k, v, ao);

    // ---- output projection + bias ----------------------------------------
    gemm_t<0, 0><<<dim3(8, 128), 256, GEMM_SMEM>>>(
        ao, wot, bo, nullptr, nullptr, nullptr, out, BATCH * NQ, DIMC, DIMC);
}

// round 17
// speedup vs baseline: 1.2282x; 1.2282x over previous
#include <cuda_runtime.h>
#include <math.h>

#define DIMC   1024
#define NHEADS 16
#define HDIM   64
#define BATCH  4
#define NQ     4096
#define NCTX   256

// Scratch (no allocations allowed) ------------------------------------------
__device__ float g_q [BATCH * NQ   * DIMC];   // 64 MB (normed+roped, tf32)
__device__ float g_k [BATCH * NCTX * DIMC];   //  4 MB (normed, tf32)
__device__ float g_v [BATCH * NCTX * DIMC];   //  4 MB (tf32)
__device__ float g_ao[BATCH * NQ   * DIMC];   // 64 MB
__device__ float g_xr[BATCH * NQ   * DIMC];   // 64 MB  x pre-rounded tf32
__device__ float g_cr[BATCH * NCTX * DIMC];   //  4 MB  c pre-rounded
__device__ float g_wt[4][DIMC * DIMC];        // 16 MB  W^T, tf32-rounded

__device__ __forceinline__ float tf32f(float f) {
    unsigned r;
    asm("cvt.rna.tf32.f32 %0, %1;" : "=r"(r) : "f"(f));
    return __uint_as_float(r);
}

#define MMA_TF32(C, a0, a1, a2, a3, b0, b1)                                   \
    asm volatile(                                                             \
        "mma.sync.aligned.m16n8k8.row.col.f32.tf32.tf32.f32 "                 \
        "{%0,%1,%2,%3}, {%4,%5,%6,%7}, {%8,%9}, {%0,%1,%2,%3};"               \
        : "+f"((C)[0]), "+f"((C)[1]), "+f"((C)[2]), "+f"((C)[3])              \
        : "r"(a0), "r"(a1), "r"(a2), "r"(a3), "r"(b0), "r"(b1))

#define LDSM4(r0, r1, r2, r3, saddr)                                          \
    asm volatile("ldmatrix.sync.aligned.m8n8.x4.shared.b16 {%0,%1,%2,%3}, [%4];" \
        : "=r"(r0), "=r"(r1), "=r"(r2), "=r"(r3) : "r"(saddr))

#define CPA16(saddr, gptr) \
    asm volatile("cp.async.cg.shared.global [%0], [%1], 16;" :: "r"(saddr), "l"(gptr))

// ===========================================================================
// Prep kernels
// ===========================================================================
__global__ __launch_bounds__(256) void round_tf32(
    const float* __restrict__ s, float* __restrict__ d, int n4)
{
    int i = blockIdx.x * blockDim.x + threadIdx.x;
    if (i < n4) {
        float4 v = ((const float4*)s)[i];
        v.x = tf32f(v.x); v.y = tf32f(v.y);
        v.z = tf32f(v.z); v.w = tf32f(v.w);
        ((float4*)d)[i] = v;
    }
}

__global__ __launch_bounds__(256) void trans_round_w(
    const float* __restrict__ s0, const float* __restrict__ s1,
    const float* __restrict__ s2, const float* __restrict__ s3,
    float* __restrict__ d)
{
    const float* s = (blockIdx.z == 0) ? s0 : (blockIdx.z == 1) ? s1
                   : (blockIdx.z == 2) ? s2 : s3;
    float* dd = d + (long)blockIdx.z * (DIMC * DIMC);
    __shared__ float t[32][33];
    int tx = threadIdx.x & 31, ty = threadIdx.x >> 5;
    int bx = blockIdx.x * 32, by = blockIdx.y * 32;
#pragma unroll
    for (int i = 0; i < 32; i += 8)
        t[ty + i][tx] = tf32f(s[(long)(by + ty + i) * DIMC + bx + tx]);
    __syncthreads();
#pragma unroll
    for (int i = 0; i < 32; i += 8)
        dd[(long)(bx + ty + i) * DIMC + by + tx] = t[tx][ty + i];
}

// ===========================================================================
// tf32 GEMM, B pre-transposed (k-major). 128x128x32 tile, 256 thr, ldmatrix.
// Templated epilogue:
//   MODE 0: (+bias) (+tf32 round if ROUNDC)
//   MODE 1: per-head RMSNorm * nw, tf32 round      (K path)
//   MODE 2: per-head RMSNorm * nw + RoPE, tf32 round (Q path)
// ===========================================================================
#define AST 36
#define STAGE_F (2 * 128 * AST)
#define STAGE_B (STAGE_F * 4)
#define GEMM_SMEM (2 * STAGE_B)          // 73728 B (also covers epilogue bufs)

template<int MODE, int ROUNDC>
__global__ __launch_bounds__(256) void gemm_t(
    const float* __restrict__ A, const float* __restrict__ Bt,
    const float* __restrict__ bias, const float* __restrict__ nw,
    const float* __restrict__ rcos, const float* __restrict__ rsin,
    float* __restrict__ C, int M, int N, int K)
{
    extern __shared__ float sh[];

    const int t    = threadIdx.x;
    const int lane = t & 31;
    const int w    = t >> 5;
    const int wm   = (w & 1) * 64;
    const int wn   = (w >> 1) * 32;
    const int m0   = blockIdx.y * 128;
    const int n0   = blockIdx.x * 128;

    const unsigned shu = (unsigned)__cvta_generic_to_shared(sh);

    float acc[4][4][4];
#pragma unroll
    for (int mt = 0; mt < 4; mt++)
#pragma unroll
        for (int nt = 0; nt < 4; nt++)
#pragma unroll
            for (int i = 0; i < 4; i++) acc[mt][nt][i] = 0.f;

#define ISSUE(s, k0)                                                          \
    {                                                                         \
        unsigned abase = shu + (s) * STAGE_B;                                 \
        unsigned bbase = abase + 128 * AST * 4;                               \
        _Pragma("unroll")                                                     \
        for (int j = 0; j < 4; j++) {                                         \
            int idx = t + j * 256;                                            \
            int r = idx >> 3, c4 = (idx & 7) << 2;                            \
            CPA16(abase + (unsigned)(r * AST + c4) * 4,                       \
                  A + (long)(m0 + r) * K + (k0) + c4);                        \
            CPA16(bbase + (unsigned)(r * AST + c4) * 4,                       \
                  Bt + (long)(n0 + r) * K + (k0) + c4);                       \
        }                                                                     \
        asm volatile("cp.async.commit_group;");                               \
    }

    const int aSel = ((lane >> 3) & 1) * 8 + (lane & 7);
    const int cSel = (lane >> 4) * 4;
    const int bRowSel = (lane >> 4) * 8 + (lane & 7);
    const int bColSel = ((lane >> 3) & 1) * 4;

    const int niter = K >> 5;
    ISSUE(0, 0);

    for (int it = 0; it < niter; it++) {
        if (it + 1 < niter) {
            ISSUE((it + 1) & 1, (it + 1) << 5);
            asm volatile("cp.async.wait_group 1;");
        } else {
            asm volatile("cp.async.wait_group 0;");
        }
        __syncthreads();

        unsigned as_u = shu + (it & 1) * STAGE_B;
        unsigned bs_u = as_u + 128 * AST * 4;

#pragma unroll
        for (int kk = 0; kk < 32; kk += 8) {
            unsigned af[4][4], bf[4][2];
#pragma unroll
            for (int mt = 0; mt < 4; mt++) {
                unsigned ad = as_u +
                    (unsigned)((wm + mt * 16 + aSel) * AST + kk + cSel) * 4;
                LDSM4(af[mt][0], af[mt][1], af[mt][2], af[mt][3], ad);
            }
#pragma unroll
            for (int p = 0; p < 2; p++) {
                unsigned bd = bs_u +
                    (unsigned)((wn + p * 16 + bRowSel) * AST + kk + bColSel) * 4;
                LDSM4(bf[2 * p][0], bf[2 * p][1], bf[2 * p + 1][0],
                      bf[2 * p + 1][1], bd);
            }
#pragma unroll
            for (int mt = 0; mt < 4; mt++)
#pragma unroll
                for (int nt = 0; nt < 4; nt++)
                    MMA_TF32(acc[mt][nt], af[mt][0], af[mt][1], af[mt][2],
                             af[mt][3], bf[nt][0], bf[nt][1]);
        }
        __syncthreads();
    }

    const int qrow = lane >> 2;

    if (MODE == 0) {
#pragma unroll
        for (int nt = 0; nt < 4; nt++) {
            int col = n0 + wn + nt * 8 + 2 * (lane & 3);
            float bb0 = bias ? bias[col]     : 0.f;
            float bb1 = bias ? bias[col + 1] : 0.f;
#pragma unroll
            for (int mt = 0; mt < 4; mt++) {
                int row = m0 + wm + mt * 16 + qrow;
                float2 r0, r1;
                r0.x = acc[mt][nt][0] + bb0; r0.y = acc[mt][nt][1] + bb1;
                r1.x = acc[mt][nt][2] + bb0; r1.y = acc[mt][nt][3] + bb1;
                if (ROUNDC) {
                    r0.x = tf32f(r0.x); r0.y = tf32f(r0.y);
                    r1.x = tf32f(r1.x); r1.y = tf32f(r1.y);
                }
                *(float2*)&C[(long)row * N + col]       = r0;
                *(float2*)&C[(long)(row + 8) * N + col] = r1;
            }
        }
    } else {
        // ---- fused RMSNorm (+RoPE) epilogue ------------------------------
        float* ssb = sh;                 // [2][128] partial sums
        float* vt  = sh + 512;           // [128][132] (MODE 2 only)
        const int ny = w >> 1;

        float ssA[4], ssB[4];
#pragma unroll
        for (int mt = 0; mt < 4; mt++) {
            float a = 0.f, b2 = 0.f;
#pragma unroll
            for (int nt = 0; nt < 4; nt++) {
                a  += acc[mt][nt][0] * acc[mt][nt][0]
                    + acc[mt][nt][1] * acc[mt][nt][1];
                b2 += acc[mt][nt][2] * acc[mt][nt][2]
                    + acc[mt][nt][3] * acc[mt][nt][3];
            }
            a  += __shfl_xor_sync(0xffffffffu, a, 1);
            a  += __shfl_xor_sync(0xffffffffu, a, 2);
            b2 += __shfl_xor_sync(0xffffffffu, b2, 1);
            b2 += __shfl_xor_sync(0xffffffffu, b2, 2);
            ssA[mt] = a; ssB[mt] = b2;
        }
        if ((lane & 3) == 0) {
#pragma unroll
            for (int mt = 0; mt < 4; mt++) {
                int rl = wm + 16 * mt + qrow;
                ssb[ny * 128 + rl]     = ssA[mt];
                ssb[ny * 128 + rl + 8] = ssB[mt];
            }
        }
        __syncthreads();

#pragma unroll
        for (int mt = 0; mt < 4; mt++) {
            int rl = wm + 16 * mt + qrow;
            float invA = rsqrtf((ssA[mt] + ssb[(ny ^ 1) * 128 + rl])
                                * (1.f / 64.f) + 1e-6f);
            float invB = rsqrtf((ssB[mt] + ssb[(ny ^ 1) * 128 + rl + 8])
                                * (1.f / 64.f) + 1e-6f);
#pragma unroll
            for (int nt = 0; nt < 4; nt++) {
                int cl = wn + nt * 8 + 2 * (lane & 3);
                float w0 = nw[cl & 63], w1 = nw[(cl + 1) & 63];
                acc[mt][nt][0] *= invA * w0;
                acc[mt][nt][1] *= invA * w1;
                acc[mt][nt][2] *= invB * w0;
                acc[mt][nt][3] *= invB * w1;
            }
        }

        if (MODE == 1) {
#pragma unroll
            for (int mt = 0; mt < 4; mt++) {
                int row = m0 + wm + 16 * mt + qrow;
#pragma unroll
                for (int nt = 0; nt < 4; nt++) {
                    int col = n0 + wn + nt * 8 + 2 * (lane & 3);
                    *(float2*)&C[(long)row * N + col] =
                        make_float2(tf32f(acc[mt][nt][0]), tf32f(acc[mt][nt][1]));
                    *(float2*)&C[(long)(row + 8) * N + col] =
                        make_float2(tf32f(acc[mt][nt][2]), tf32f(acc[mt][nt][3]));
                }
            }
        } else {
            // Q path: RoPE via smem tile exchange (d <-> d^32)
#pragma unroll
            for (int mt = 0; mt < 4; mt++) {
                int rl = wm + 16 * mt + qrow;
#pragma unroll
                for (int nt = 0; nt < 4; nt++) {
                    int cl = wn + nt * 8 + 2 * (lane & 3);
                    *(float2*)&vt[rl * 132 + cl] =
                        make_float2(acc[mt][nt][0], acc[mt][nt][1]);
                    *(float2*)&vt[(rl + 8) * 132 + cl] =
                        make_float2(acc[mt][nt][2], acc[mt][nt][3]);
                }
            }
            __syncthreads();
#pragma unroll
            for (int mt = 0; mt < 4; mt++) {
                int rl = wm + 16 * mt + qrow;
                int nA = (m0 + rl)     & (NQ - 1);
                int nB = (m0 + rl + 8) & (NQ - 1);
#pragma unroll
                for (int nt = 0; nt < 4; nt++) {
                    int cl = wn + nt * 8 + 2 * (lane & 3);
                    int d  = cl & 63;
                    float2 cA = *(const float2*)&rcos[nA * 64 + d];
                    float2 sA = *(const float2*)&rsin[nA * 64 + d];
                    float2 cB = *(const float2*)&rcos[nB * 64 + d];
                    float2 sB = *(const float2*)&rsin[nB * 64 + d];
                    float p0A = vt[rl * 132 + (cl ^ 32)];
                    float p1A = vt[rl * 132 + ((cl + 1) ^ 32)];
                    float p0B = vt[(rl + 8) * 132 + (cl ^ 32)];
                    float p1B = vt[(rl + 8) * 132 + ((cl + 1) ^ 32)];
                    float sgn = (cl & 32) ? 1.f : -1.f;
                    float o0A = acc[mt][nt][0] * cA.x + sgn * p0A * sA.x;
                    float o1A = acc[mt][nt][1] * cA.y + sgn * p1A * sA.y;
                    float o0B = acc[mt][nt][2] * cB.x + sgn * p0B * sB.x;
                    float o1B = acc[mt][nt][3] * cB.y + sgn * p1B * sB.y;
                    int row = m0 + rl, col = n0 + cl;
                    *(float2*)&C[(long)row * N + col] =
                        make_float2(tf32f(o0A), tf32f(o1A));
                    *(float2*)&C[(long)(row + 8) * N + col] =
                        make_float2(tf32f(o0B), tf32f(o1B));
                }
            }
        }
    }
}

// ===========================================================================
// Register-resident tensor-core attention, cp.async staged.
// CTA = 128 q-rows x 1 head x 1 batch; warp w owns 16 q-rows x 256 ctx.
// Q+K committed as group 0, V as group 1: V load latency hides behind
// QK^T + softmax (wait_group 0 only after softmax).
// QK^T -> regs; quad-shuffle softmax; PV via per-warp smem P (aliases Qs/Ks)
// + ldmatrix a-frags, V b-frags via conflict-free scalar LDS (row-major Vs).
// ===========================================================================
#define ATQ 0
#define ATK (128 * 68)                   // 8704
#define ATV (ATK + 256 * 68)             // 26112
#define ATT_FLOATS (ATV + 256 * 68)      // 43520 floats = 174080 B
#define PSTR 132
#define PBUF_W (16 * PSTR)               // 2112 floats/warp; aliases Qs+Ks

__global__ __launch_bounds__(256) void attn_mma(
    const float* __restrict__ q, const float* __restrict__ k,
    const float* __restrict__ v, float* __restrict__ ao)
{
    extern __shared__ float sm[];
    float* Vs = sm + ATV;
    const unsigned shu  = (unsigned)__cvta_generic_to_shared(sm);
    const unsigned qs_u = shu;
    const unsigned ks_u = shu + ATK * 4;
    const unsigned vs_u = shu + ATV * 4;

    const int t  = threadIdx.x;
    const int nt = blockIdx.x, h = blockIdx.y, b = blockIdx.z;
    const int qrow0  = b * NQ + nt * 128;
    const int kvrow0 = b * NCTX;
    const int cbase  = h * HDIM;

    // ---- stage Q + K (group 0) via cp.async ------------------------------
#pragma unroll
    for (int j = 0; j < 8; j++) {               // Q: 128 rows x 16 chunks
        int i4 = t + j * 256;
        int i = i4 >> 4, d4 = (i4 & 15) << 2;
        CPA16(qs_u + (unsigned)(i * 68 + d4) * 4,
              q + (long)(qrow0 + i) * DIMC + cbase + d4);
    }
#pragma unroll
    for (int j = 0; j < 16; j++) {              // K: 256 rows x 16 chunks
        int i4 = t + j * 256;
        int i = i4 >> 4, d4 = (i4 & 15) << 2;
        CPA16(ks_u + (unsigned)(i * 68 + d4) * 4,
              k + (long)(kvrow0 + i) * DIMC + cbase + d4);
    }
    asm volatile("cp.async.commit_group;");
    // ---- stage V (group 1, waited only after softmax) --------------------
#pragma unroll
    for (int j = 0; j < 16; j++) {              // V: 256 rows x 16 chunks
        int i4 = t + j * 256;
        int i = i4 >> 4, d4 = (i4 & 15) << 2;
        CPA16(vs_u + (unsigned)(i * 68 + d4) * 4,
              v + (long)(kvrow0 + i) * DIMC + cbase + d4);
    }
    asm volatile("cp.async.commit_group;");

    asm volatile("cp.async.wait_group 1;");     // Q + K ready (V in flight)
    __syncthreads();

    const int lane = t & 31;
    const int w    = t >> 5;
    const int qr   = w * 16;

    const int aSel = ((lane >> 3) & 1) * 8 + (lane & 7);
    const int cSel = (lane >> 4) * 4;
    const int bRowSel = (lane >> 4) * 8 + (lane & 7);
    const int bColSel = ((lane >> 3) & 1) * 4;

    // ---- S = Q K^T (16 x 256 per warp, in registers) ---------------------
    float acc[32][4];
#pragma unroll
    for (int n = 0; n < 32; n++)
#pragma unroll
        for (int i = 0; i < 4; i++) acc[n][i] = 0.f;

#pragma unroll
    for (int ks = 0; ks < 8; ks++) {
        int d0 = ks * 8;
        unsigned a0, a1, a2, a3;
        LDSM4(a0, a1, a2, a3,
              qs_u + (unsigned)((qr + aSel) * 68 + d0 + cSel) * 4);
#pragma unroll
        for (int p = 0; p < 16; p++) {
            unsigned b0, b1, b2, b3;
            LDSM4(b0, b1, b2, b3,
                  ks_u + (unsigned)((p * 16 + bRowSel) * 68 + d0 + bColSel) * 4);
            MMA_TF32(acc[2 * p],     a0, a1, a2, a3, b0, b1);
            MMA_TF32(acc[2 * p + 1], a0, a1, a2, a3, b2, b3);
        }
    }
    __syncthreads();   // Qs/Ks reads done (P buffers alias them)

    // ---- softmax (rows on lane-quads) ------------------------------------
    const float scale = 0.125f;
    float mxA = -1e30f, mxB = -1e30f;
#pragma unroll
    for (int n = 0; n < 32; n++) {
        mxA = fmaxf(mxA, fmaxf(acc[n][0], acc[n][1]));
        mxB = fmaxf(mxB, fmaxf(acc[n][2], acc[n][3]));
    }
    mxA = fmaxf(mxA, __shfl_xor_sync(0xffffffffu, mxA, 1));
    mxA = fmaxf(mxA, __shfl_xor_sync(0xffffffffu, mxA, 2));
    mxB = fmaxf(mxB, __shfl_xor_sync(0xffffffffu, mxB, 1));
    mxB = fmaxf(mxB, __shfl_xor_sync(0xffffffffu, mxB, 2));
    mxA *= scale; mxB *= scale;

    float sA = 0.f, sB = 0.f;
#pragma unroll
    for (int n = 0; n < 32; n++) {
        acc[n][0] = __expf(acc[n][0] * scale - mxA); sA += acc[n][0];
        acc[n][1] = __expf(acc[n][1] * scale - mxA); sA += acc[n][1];
        acc[n][2] = __expf(acc[n][2] * scale - mxB); sB += acc[n][2];
        acc[n][3] = __expf(acc[n][3] * scale - mxB); sB += acc[n][3];
    }
    sA += __shfl_xor_sync(0xffffffffu, sA, 1);
    sA += __shfl_xor_sync(0xffffffffu, sA, 2);
    sB += __shfl_xor_sync(0xffffffffu, sB, 1);
    sB += __shfl_xor_sync(0xffffffffu, sB, 2);
    float invA = 1.f / sA, invB = 1.f / sB;
#pragma unroll
    for (int n = 0; n < 32; n++) {
        acc[n][0] = tf32f(acc[n][0] * invA);
        acc[n][1] = tf32f(acc[n][1] * invA);
        acc[n][2] = tf32f(acc[n][2] * invB);
        acc[n][3] = tf32f(acc[n][3] * invB);
    }

    asm volatile("cp.async.wait_group 0;");     // V landed (own copies)
    __syncthreads();                            // ... and everyone else's

    // ---- O = P V: P staged per-warp + ldmatrix; V b-frags scalar LDS -----
    float* Pb = sm + w * PBUF_W;
    const unsigned pb_u = shu + (unsigned)(w * PBUF_W) * 4;

    float oacc[8][4];
#pragma unroll
    for (int dt = 0; dt < 8; dt++)
#pragma unroll
        for (int i = 0; i < 4; i++) oacc[dt][i] = 0.f;

#pragma unroll
    for (int hf = 0; hf < 2; hf++) {
#pragma unroll
        for (int nl = 0; nl < 16; nl++) {
            int n = 16 * hf + nl;
            int base = (lane >> 2) * PSTR + nl * 8 + 2 * (lane & 3);
            *(float2*)&Pb[base]            = make_float2(acc[n][0], acc[n][1]);
            *(float2*)&Pb[base + 8 * PSTR] = make_float2(acc[n][2], acc[n][3]);
        }
        __syncwarp();
#pragma unroll
        for (int ksl = 0; ksl < 16; ksl++) {
            unsigned a0, a1, a2, a3;
            LDSM4(a0, a1, a2, a3,
                  pb_u + (unsigned)(aSel * PSTR + ksl * 8 + cSel) * 4);
            int j0 = 128 * hf + ksl * 8;
            int vb0 = (j0 + (lane & 3)) * 68 + (lane >> 2);
            int vb1 = vb0 + 4 * 68;
#pragma unroll
            for (int dt = 0; dt < 8; dt++) {
                unsigned b0 = __float_as_uint(Vs[vb0 + dt * 8]);
                unsigned b1 = __float_as_uint(Vs[vb1 + dt * 8]);
                MMA_TF32(oacc[dt], a0, a1, a2, a3, b0, b1);
            }
        }
        __syncwarp();   // P reads done before next half overwrites
    }

    // store O (tf32-rounded; feeds O-proj GEMM)
#pragma unroll
    for (int dt = 0; dt < 8; dt++) {
        long row = qrow0 + qr + (lane >> 2);
        int  col = cbase + dt * 8 + 2 * (lane & 3);
        float2 r0, r1;
        r0.x = tf32f(oacc[dt][0]); r0.y = tf32f(oacc[dt][1]);
        r1.x = tf32f(oacc[dt][2]); r1.y = tf32f(oacc[dt][3]);
        *(float2*)&ao[row * DIMC + col]       = r0;
        *(float2*)&ao[(row + 8) * DIMC + col] = r1;
    }
}

// ---------------------------------------------------------------------------
extern "C" void kernel_launch(void* const* d_in, const int* in_sizes, int n_in,
                              void* d_out, int out_size)
{
    const float* x  = (const float*)d_in[0];
    const float* c  = (const float*)d_in[1];
    const float* rc = (const float*)d_in[2];
    const float* rs = (const float*)d_in[3];
    const float* Wq = (const float*)d_in[4];
    const float* Wk = (const float*)d_in[5];
    const float* Wv = (const float*)d_in[6];
    const float* Wo = (const float*)d_in[7];
    const float* bo = (const float*)d_in[8];
    const float* qw = (const float*)d_in[9];
    const float* kw = (const float*)d_in[10];
    float* out = (float*)d_out;

    float *q, *k, *v, *ao, *xr, *cr, *wt;
    cudaGetSymbolAddress((void**)&q,  g_q);
    cudaGetSymbolAddress((void**)&k,  g_k);
    cudaGetSymbolAddress((void**)&v,  g_v);
    cudaGetSymbolAddress((void**)&ao, g_ao);
    cudaGetSymbolAddress((void**)&xr, g_xr);
    cudaGetSymbolAddress((void**)&cr, g_cr);
    cudaGetSymbolAddress((void**)&wt, g_wt);

    cudaFuncSetAttribute(gemm_t<0, 0>, cudaFuncAttributeMaxDynamicSharedMemorySize, GEMM_SMEM);
    cudaFuncSetAttribute(gemm_t<0, 1>, cudaFuncAttributeMaxDynamicSharedMemorySize, GEMM_SMEM);
    cudaFuncSetAttribute(gemm_t<1, 1>, cudaFuncAttributeMaxDynamicSharedMemorySize, GEMM_SMEM);
    cudaFuncSetAttribute(gemm_t<2, 1>, cudaFuncAttributeMaxDynamicSharedMemorySize, GEMM_SMEM);
    cudaFuncSetAttribute(attn_mma, cudaFuncAttributeMaxDynamicSharedMemorySize,
                         ATT_FLOATS * (int)sizeof(float));

    // ---- prep: round activations, transpose+round weights ----------------
    {
        int n4x = BATCH * NQ * DIMC / 4;
        round_tf32<<<n4x / 256, 256>>>(x, xr, n4x);
        int n4c = BATCH * NCTX * DIMC / 4;
        round_tf32<<<n4c / 256, 256>>>(c, cr, n4c);
        trans_round_w<<<dim3(32, 32, 4), 256>>>(Wq, Wk, Wv, Wo, wt);
    }
    const float* wqt = wt;
    const float* wkt = wt + (long)1 * DIMC * DIMC;
    const float* wvt = wt + (long)2 * DIMC * DIMC;
    const float* wot = wt + (long)3 * DIMC * DIMC;

    // ---- Q projection + fused RMSNorm + RoPE -----------------------------
    gemm_t<2, 1><<<dim3(8, 128), 256, GEMM_SMEM>>>(
        xr, wqt, nullptr, qw, rc, rs, q, BATCH * NQ, DIMC, DIMC);

    // ---- K (fused RMSNorm) and V (plain, tf32-rounded) -------------------
    gemm_t<1, 1><<<dim3(8, 8), 256, GEMM_SMEM>>>(
        cr, wkt, nullptr, kw, nullptr, nullptr, k, BATCH * NCTX, DIMC, DIMC);
    gemm_t<0, 1><<<dim3(8, 8), 256, GEMM_SMEM>>>(
        cr, wvt, nullptr, nullptr, nullptr, nullptr, v, BATCH * NCTX, DIMC, DIMC);

    // ---- attention --------------------------------------------------------
    attn_mma<<<dim3(NQ / 128, NHEADS, BATCH), 256,
               ATT_FLOATS * (int)sizeof(float)>>>(q, k, v, ao);

    // ---- output projection + bias ----------------------------------------
    gemm_t<0, 0><<<dim3(8, 128), 256, GEMM_SMEM>>>(
        ao, wot, bo, nullptr, nullptr, nullptr, out, BATCH * NQ, DIMC, DIMC);
}